// round 15
// baseline (speedup 1.0000x reference)
#include <cuda_runtime.h>
#include <math.h>

#define B_ 64
#define T_ 2048
#define I_ 64
#define S_ 128
#define O_ 64
#define LN_EPS 1e-5f
#define TP 2052
#define REC_DYN (160*1024)
#define AUX_DYN (96*1024)

typedef unsigned long long ull;

__device__ float g_GX[2ull*B_*TP*S_];
__device__ float g_H [B_*T_*S_];
__device__ float g_xsum[B_*I_];
__device__ float g_boSum[B_*O_];
__device__ float g_boSsq[B_*O_];
__device__ float g_S1, g_S2, g_SA;
__device__ float g_hb[B_*136];
__device__ float g_red[B_*32];
__device__ float g_hbm[B_*256];
__device__ float g_ag[S_], g_ab[S_];

__device__ __forceinline__ ull pack2(float lo, float hi) {
    ull r; asm("mov.b64 %0,{%1,%2};" : "=l"(r) : "f"(lo), "f"(hi)); return r;
}
__device__ __forceinline__ void unpack2(ull v, float &lo, float &hi) {
    asm("mov.b64 {%0,%1},%2;" : "=f"(lo), "=f"(hi) : "l"(v));
}
__device__ __forceinline__ ull ffma2(ull a, ull b, ull c) {
    ull d; asm("fma.rn.f32x2 %0,%1,%2,%3;" : "=l"(d) : "l"(a), "l"(b), "l"(c)); return d;
}

__global__ void zeroK() {
    int i = blockIdx.x * blockDim.x + threadIdx.x;
    if (i < B_*O_) { g_boSum[i] = 0.f; g_boSsq[i] = 0.f; }
    if (i < B_*I_) g_xsum[i] = 0.f;
    if (i == 0) { g_S1 = 0.f; g_S2 = 0.f; g_SA = 0.f; }
}

// precompute agI (A gamma row-sum / S) and abv (A beta row-sum)
__global__ __launch_bounds__(128) void precompK(
    const float* __restrict__ A, const float* __restrict__ gamma,
    const float* __restrict__ beta)
{
    int s = threadIdx.x;
    const float* ar = A + s*S_;
    float ag = 0.f, ab = 0.f;
#pragma unroll 16
    for (int k = 0; k < S_; k++) { ag += ar[k]*gamma[k]; ab += ar[k]*beta[k]; }
    g_ag[s] = ag * (1.f/(float)S_);
    g_ab[s] = ab;
}

// ---------- gateSegK: 32-timestep tiles, fused G+B, 512 CTAs per seg ----------
__global__ __launch_bounds__(128) void gateSegK(
    const float* __restrict__ x, const float* __restrict__ Wsel,
    const float* __restrict__ bsel, const float* __restrict__ Bm, int seg)
{
    extern __shared__ char fill[]; (void)fill;
    __shared__ __align__(16) float xs[2][512];
    __shared__ __align__(16) float xred[128];
    int tid = threadIdx.x;
    int s = tid;
    ull w2G[32], w2B[32];
#pragma unroll
    for (int k = 0; k < 32; k++) {
        w2G[k] = pack2(Wsel[s*I_ + 2*k], Wsel[s*I_ + 2*k+1]);
        w2B[k] = pack2(Bm[s*I_ + 2*k],  Bm[s*I_ + 2*k+1]);
    }
    float bias = bsel[s];

    int b = blockIdx.x >> 3;
    int t0 = (seg << 8) + ((blockIdx.x & 7) << 5);
    const float* xseg = x + ((size_t)b*T_ + t0)*I_;
    float2* outp = ((float2*)g_GX) + (size_t)b*TP*S_ + s;
    float xacc = 0.f;
    int ci = tid & 63, r0 = (tid >> 6) * 4;

    ((float4*)xs[0])[tid] = ((const float4*)xseg)[tid];
    __syncthreads();

    for (int st = 0; st < 4; st++) {
        int cur = st & 1;
        bool more = (st < 3);
        float4 rx = make_float4(0.f, 0.f, 0.f, 0.f);
        if (more) rx = ((const float4*)(xseg + (size_t)(st+1)*512))[tid];
        int tb = t0 + st*8;
#pragma unroll
        for (int r = 0; r < 8; r++) {
            const ulonglong2* xv = (const ulonglong2*)(xs[cur] + r*64);
            ull g0=0, g1=0, b0=0, b1=0;
#pragma unroll
            for (int i = 0; i < 16; i += 2) {
                ulonglong2 p = xv[i], q = xv[i+1];
                g0 = ffma2(w2G[2*i+0], p.x, g0); b0 = ffma2(w2B[2*i+0], p.x, b0);
                g1 = ffma2(w2G[2*i+1], p.y, g1); b1 = ffma2(w2B[2*i+1], p.y, b1);
                g0 = ffma2(w2G[2*i+2], q.x, g0); b0 = ffma2(w2B[2*i+2], q.x, b0);
                g1 = ffma2(w2G[2*i+3], q.y, g1); b1 = ffma2(w2B[2*i+3], q.y, b1);
            }
            float u,v,e,f;
            unpack2(g0,u,v); unpack2(g1,e,f);
            float dg = (u+v)+(e+f);
            unpack2(b0,u,v); unpack2(b1,e,f);
            float db = (u+v)+(e+f);
            float gt = 1.f/(1.f + __expf(-(dg + bias)));
            outp[(size_t)(tb + r)*S_] = make_float2(gt, db);
        }
        xacc += (xs[cur][(r0+0)*64 + ci] + xs[cur][(r0+1)*64 + ci])
              + (xs[cur][(r0+2)*64 + ci] + xs[cur][(r0+3)*64 + ci]);
        __syncthreads();
        if (more) ((float4*)xs[cur ^ 1])[tid] = rx;
        __syncthreads();
    }
    xred[tid] = xacc;
    __syncthreads();
    if (tid < 64) atomicAdd(&g_xsum[b*I_ + tid], xred[tid] + xred[tid+64]);
}

__global__ __launch_bounds__(128) void selFin(
    const float* __restrict__ Wsel, const float* __restrict__ bsel)
{
    __shared__ float part[4];
    int tid = threadIdx.x, b = blockIdx.x;
    float acc = bsel[tid];
    const float invT = 1.0f/(float)T_;
    const float* w  = Wsel + tid*I_;
    const float* xm = g_xsum + b*I_;
#pragma unroll 8
    for (int k = 0; k < I_; k++) acc += xm[k]*invT*w[k];
    float sg = 1.f/(1.f + __expf(-acc));
#pragma unroll
    for (int off = 16; off > 0; off >>= 1) sg += __shfl_xor_sync(0xffffffffu, sg, off);
    if ((tid & 31) == 0) part[tid >> 5] = sg;
    __syncthreads();
    if (tid == 0) atomicAdd(&g_SA, (part[0]+part[1]) + (part[2]+part[3]));
}

// ---------- recSegK: 256 steps per launch, state persisted in globals ----------
__global__ __launch_bounds__(256, 1) void recSegK(
    const float* __restrict__ A, const float* __restrict__ gamma,
    const float* __restrict__ beta, int seg)
{
    extern __shared__ char fill[]; (void)fill;
    __shared__ __align__(16) float hbuf[2][136];
    __shared__ __align__(16) float2 red[2][16];
    int tid = threadIdx.x, b = blockIdx.x;
    int w = tid >> 5, lane = tid & 31;
    int s = (w << 4) + (lane >> 1);
    int q = lane & 1;
    int hoff = s + ((s & 64) >> 4);
    const float invS = 1.f/(float)S_;
    int t0 = seg << 8;

    float gam_s = gamma[s], bet_s = beta[s];
    float gamI = gam_s * invS;
    float agI = g_ag[s], abv = g_ab[s];
    ull a2[32];
    {
        const float* ar = A + s*S_ + q*64;
        const float* gm = gamma + q*64;
#pragma unroll
        for (int k = 0; k < 32; k++)
            a2[k] = pack2(ar[2*k]*gm[2*k], ar[2*k+1]*gm[2*k+1]);
    }

    float hbmine;
    if (seg == 0) {
        if (tid < 136) { hbuf[0][tid] = 0.f; hbuf[1][tid] = 0.f; }
        if (tid < 32)  ((float2*)red)[tid] = make_float2(0.f, 0.f);
        hbmine = 0.f;
    } else {
        if (tid < 136) hbuf[0][tid] = g_hb[b*136 + tid];
        if (tid < 32)  ((float*)red)[tid] = g_red[b*32 + tid];
        hbmine = g_hbm[b*256 + tid];
    }

    const float2* GX = ((const float2*)g_GX) + (size_t)b*TP*S_ + s;
    float* Hp = g_H + (size_t)b*T_*S_ + s;
    float2 gx[4];
#pragma unroll
    for (int j = 0; j < 4; j++) gx[j] = GX[(size_t)(t0 + j)*S_];
    __syncthreads();

    int p = 0;
#pragma unroll 4
    for (int t = t0; t < t0 + 256; t++) {
        float2 gxv = gx[t & 3];
        gx[t & 3] = GX[(size_t)(t + 4)*S_];

        const float4* rp = (const float4*)red[p];
        float4 r0 = rp[0], r1 = rp[1], r2 = rp[2], r3 = rp[3];
        float4 r4 = rp[4], r5 = rp[5], r6 = rp[6], r7 = rp[7];
        float sum = (((r0.x + r0.z) + (r1.x + r1.z)) + ((r2.x + r2.z) + (r3.x + r3.z)))
                  + (((r4.x + r4.z) + (r5.x + r5.z)) + ((r6.x + r6.z) + (r7.x + r7.z)));
        float ssq = (((r0.y + r0.w) + (r1.y + r1.w)) + ((r2.y + r2.w) + (r3.y + r3.w)))
                  + (((r4.y + r4.w) + (r5.y + r5.w)) + ((r6.y + r6.w) + (r7.y + r7.w)));
        float mu  = sum * invS;
        float ve  = fmaf(ssq, invS, LN_EPS) - mu*mu;
        float rin = rsqrtf(ve);

        const ulonglong2* hv = (const ulonglong2*)(&hbuf[p][q*68]);
        ull ac0 = 0, ac1 = 0, ac2 = 0, ac3 = 0;
#pragma unroll
        for (int i = 0; i < 16; i += 4) {
            ulonglong2 pv = hv[i], rv = hv[i+1], uv = hv[i+2], vv = hv[i+3];
            ac0 = ffma2(a2[2*i+0], pv.x, ac0); ac1 = ffma2(a2[2*i+1], pv.y, ac1);
            ac2 = ffma2(a2[2*i+2], rv.x, ac2); ac3 = ffma2(a2[2*i+3], rv.y, ac3);
            ac0 = ffma2(a2[2*i+4], uv.x, ac0); ac1 = ffma2(a2[2*i+5], uv.y, ac1);
            ac2 = ffma2(a2[2*i+6], vv.x, ac2); ac3 = ffma2(a2[2*i+7], vv.y, ac3);
        }
        float p0,p1,p2,p3,p4,p5,p6,p7;
        unpack2(ac0,p0,p1); unpack2(ac1,p2,p3); unpack2(ac2,p4,p5); unpack2(ac3,p6,p7);
        float dmine = ((p0+p1)+(p2+p3)) + ((p4+p5)+(p6+p7));
        float dfull = dmine + __shfl_xor_sync(0xffffffffu, dmine, 1);

        float abx  = (t > 0) ? (abv + gxv.y) : gxv.y;
        float preh = hbmine * gam_s;
        float hpn = (t > 0) ? fmaf(fmaf(-sum, gamI, preh), rin, bet_s) : 0.f;
        float nextraw = fmaf(fmaf(-sum, agI, dfull), rin, abx);
        float hb = fmaf(gxv.x, nextraw - hpn, hpn);
        if (t > 0 && !q) Hp[(size_t)(t-1)*S_] = hpn;
        if (!q) hbuf[p ^ 1][hoff] = hb;
        hbmine = hb;

        float s1 = hb, s2 = hb*hb;
#pragma unroll
        for (int off = 16; off > 2; off >>= 1) {
            s1 += __shfl_xor_sync(0xffffffffu, s1, off);
            s2 += __shfl_xor_sync(0xffffffffu, s2, off);
        }
        if ((lane & 0x1D) == 0) red[p ^ 1][2*w + (lane >> 1)] = make_float2(s1, s2);
        __syncthreads();
        p ^= 1;
    }
    // p == 0 here; latest state in hbuf[0], stats in red[0]
    if (seg == 7) {
        const float4* rp = (const float4*)red[0];
        float4 r0 = rp[0], r1 = rp[1], r2 = rp[2], r3 = rp[3];
        float4 r4 = rp[4], r5 = rp[5], r6 = rp[6], r7 = rp[7];
        float sum = (((r0.x + r0.z) + (r1.x + r1.z)) + ((r2.x + r2.z) + (r3.x + r3.z)))
                  + (((r4.x + r4.z) + (r5.x + r5.z)) + ((r6.x + r6.z) + (r7.x + r7.z)));
        float ssq = (((r0.y + r0.w) + (r1.y + r1.w)) + ((r2.y + r2.w) + (r3.y + r3.w)))
                  + (((r4.y + r4.w) + (r5.y + r5.w)) + ((r6.y + r6.w) + (r7.y + r7.w)));
        float mu  = sum * invS;
        float ve  = fmaf(ssq, invS, LN_EPS) - mu*mu;
        float rin = rsqrtf(ve);
        float hpn = fmaf(fmaf(-sum, gamI, hbmine*gam_s), rin, bet_s);
        if (!q) Hp[(size_t)(T_-1)*S_] = hpn;
    } else {
        if (tid < 136) g_hb[b*136 + tid] = hbuf[0][tid];
        if (tid < 32)  g_red[b*32 + tid] = ((float*)red)[tid];
        g_hbm[b*256 + tid] = hbmine;
    }
}

// ---------- outSegK: 32-timestep tiles, hf-split + register prefetch ----------
__global__ __launch_bounds__(128) void outSegK(
    const float* __restrict__ x, const float* __restrict__ C,
    const float* __restrict__ D, float* __restrict__ out, int seg)
{
    extern __shared__ char fill[]; (void)fill;
    __shared__ __align__(16) float Hs[512];
    __shared__ __align__(16) float xsO[256];
    __shared__ __align__(16) float Ysf[4][64];
    __shared__ __align__(16) float Ys2f[4][64];
    __shared__ __align__(16) float ypS[64];

    int tid = threadIdx.x;
    int b = blockIdx.x >> 3;
    int t0 = (seg << 8) + ((blockIdx.x & 7) << 5);
    int o = tid & 63, hf = tid >> 6;
    int w = tid >> 5, lane = tid & 31;

    ull c2[32], d2[16];
#pragma unroll
    for (int k = 0; k < 32; k++)
        c2[k] = pack2(C[o*S_ + hf*64 + 2*k], C[o*S_ + hf*64 + 2*k+1]);
#pragma unroll
    for (int k = 0; k < 16; k++)
        d2[k] = pack2(D[o*I_ + hf*32 + 2*k], D[o*I_ + hf*32 + 2*k+1]);
    float* dsth = hf ? &Ys2f[0][0] : &Ysf[0][0];
    float boS=0.f, boQ=0.f, nrmAcc=0.f, difAcc=0.f, ylastR=0.f;

    const float* Hb = g_H + (size_t)b*T_*S_;
    const float* xb = x + (size_t)b*T_*I_;

    if (t0 > 0) {
        Hs[tid] = Hb[(size_t)(t0-1)*S_ + tid];
        if (tid < 64) xsO[tid] = xb[(size_t)(t0-1)*I_ + tid];
        __syncthreads();
        {
            const ull* hv = (const ull*)(Hs + hf*64);
            const ull* xv = (const ull*)(xsO + hf*32);
            ull a0=0, a1=0;
#pragma unroll
            for (int k = 0; k < 32; k += 2) {
                a0 = ffma2(c2[k], hv[k], a0); a1 = ffma2(c2[k+1], hv[k+1], a1);
            }
#pragma unroll
            for (int k = 0; k < 16; k += 2) {
                a0 = ffma2(d2[k], xv[k], a0); a1 = ffma2(d2[k+1], xv[k+1], a1);
            }
            float u,v,e,f2; unpack2(a0,u,v); unpack2(a1,e,f2);
            dsth[o] = (u+v)+(e+f2);
        }
        __syncthreads();
        if (tid < 64) ylastR = Ysf[0][tid] + Ys2f[0][tid];
    }

    float pH[4], px0, px1;
#pragma unroll
    for (int j = 0; j < 4; j++) pH[j] = Hb[(size_t)(t0 + j)*S_ + tid];
    px0 = xb[(size_t)(t0 +     (tid >> 6))*I_ + o];
    px1 = xb[(size_t)(t0 + 2 + (tid >> 6))*I_ + o];

    for (int g = 0; g < 8; g++) {
        int tbase = t0 + (g << 2);
        __syncthreads();
        if (tid < 64) ypS[tid] = ylastR;
#pragma unroll
        for (int j = 0; j < 4; j++) Hs[j*128 + tid] = pH[j];
        xsO[tid]       = px0;
        xsO[tid + 128] = px1;
        __syncthreads();

        if (g + 1 < 8) {
            int tn = tbase + 4;
#pragma unroll
            for (int j = 0; j < 4; j++) pH[j] = Hb[(size_t)(tn + j)*S_ + tid];
            px0 = xb[(size_t)(tn +     (tid >> 6))*I_ + o];
            px1 = xb[(size_t)(tn + 2 + (tid >> 6))*I_ + o];
        }
#pragma unroll
        for (int r = 0; r < 4; r++) {
            const ull* hv = (const ull*)(Hs + r*128 + hf*64);
            const ull* xv = (const ull*)(xsO + r*64 + hf*32);
            ull a0=0, a1=0, a2b=0, a3=0;
#pragma unroll
            for (int k = 0; k < 32; k += 4) {
                a0  = ffma2(c2[k],   hv[k],   a0);
                a1  = ffma2(c2[k+1], hv[k+1], a1);
                a2b = ffma2(c2[k+2], hv[k+2], a2b);
                a3  = ffma2(c2[k+3], hv[k+3], a3);
            }
#pragma unroll
            for (int k = 0; k < 16; k += 4) {
                a0  = ffma2(d2[k],   xv[k],   a0);
                a1  = ffma2(d2[k+1], xv[k+1], a1);
                a2b = ffma2(d2[k+2], xv[k+2], a2b);
                a3  = ffma2(d2[k+3], xv[k+3], a3);
            }
            float u,v,e,f2,m,n,pp,qq;
            unpack2(a0,u,v); unpack2(a1,e,f2); unpack2(a2b,m,n); unpack2(a3,pp,qq);
            dsth[r*64 + o] = ((u+v)+(e+f2)) + ((m+n)+(pp+qq));
        }
        __syncthreads();
#pragma unroll
        for (int rr = 0; rr < 2; rr++) {
            int r = hf + rr*2;
            float y = Ysf[r][o] + Ys2f[r][o];
            Ysf[r][o] = y;
            boS += y; boQ += y*y;
            if (tbase + r == T_-1) out[b*O_ + o] = y;
        }
        __syncthreads();
        {
            float y0 = Ysf[w][lane], y1 = Ysf[w][lane+32];
            float p0, p1;
            if (w == 0) { p0 = ypS[lane]; p1 = ypS[lane+32]; }
            else        { p0 = Ysf[w-1][lane]; p1 = Ysf[w-1][lane+32]; }
            float sn = y0*y0 + y1*y1;
            float d0 = y0 - p0, d1 = y1 - p1;
            float dn = d0*d0 + d1*d1;
#pragma unroll
            for (int off = 16; off > 0; off >>= 1) {
                sn += __shfl_xor_sync(0xffffffffu, sn, off);
                dn += __shfl_xor_sync(0xffffffffu, dn, off);
            }
            if (lane == 0) {
                nrmAcc += sqrtf(sn);
                if (tbase + w > 0) difAcc += sqrtf(dn);
            }
            if (tid < 64) ylastR = Ysf[3][tid];
        }
    }

    if (lane == 0) { atomicAdd(&g_S2, nrmAcc); atomicAdd(&g_S1, difAcc); }
    __syncthreads();
    Hs[tid] = boS;
    __syncthreads();
    if (tid < 64) atomicAdd(&g_boSum[b*O_ + tid], Hs[tid] + Hs[tid+64]);
    __syncthreads();
    Hs[tid] = boQ;
    __syncthreads();
    if (tid < 64) atomicAdd(&g_boSsq[b*O_ + tid], Hs[tid] + Hs[tid+64]);
}

__global__ void finK(float* __restrict__ out)
{
    __shared__ float part[8];
    int tid = threadIdx.x;
    float acc = 0.f;
    for (int idx = tid; idx < B_*O_; idx += 256) {
        float sum = g_boSum[idx], ssq = g_boSsq[idx];
        float var = (ssq - sum*sum*(1.f/T_)) * (1.f/(T_ - 1));
        acc += sqrtf(fmaxf(var, 0.f));
    }
#pragma unroll
    for (int off = 16; off > 0; off >>= 1) acc += __shfl_xor_sync(0xffffffffu, acc, off);
    if ((tid & 31) == 0) part[tid >> 5] = acc;
    __syncthreads();
    if (tid == 0) {
        float tot = 0.f;
#pragma unroll
        for (int k = 0; k < 8; k++) tot += part[k];
        out[4096] = 1.f / (1.f + g_S1 / (float)(B_*(T_-1)));
        out[4097] = g_S2 / (float)(B_*T_);
        out[4098] = g_SA / (float)(B_*S_);
        out[4099] = tot  / (float)(B_*O_);
    }
}

extern "C" void kernel_launch(void* const* d_in, const int* in_sizes, int n_in,
                              void* d_out, int out_size)
{
    const float* x     = (const float*)d_in[0];
    const float* A     = (const float*)d_in[1];
    const float* Bm    = (const float*)d_in[2];
    const float* C     = (const float*)d_in[3];
    const float* D     = (const float*)d_in[4];
    const float* Wsel  = (const float*)d_in[5];
    const float* bsel  = (const float*)d_in[6];
    const float* gamma = (const float*)d_in[7];
    const float* beta  = (const float*)d_in[8];
    float* out = (float*)d_out;

    static int inited = 0;
    static cudaStream_t sA, sB, sR;
    static cudaEvent_t evFork, evG[8], evR[8], evJA, evJB, evJR;
    if (!inited) {
        int lo, hi;
        cudaDeviceGetStreamPriorityRange(&lo, &hi);
        cudaStreamCreateWithPriority(&sA, cudaStreamNonBlocking, lo);
        cudaStreamCreateWithPriority(&sB, cudaStreamNonBlocking, lo);
        cudaStreamCreateWithPriority(&sR, cudaStreamNonBlocking, hi);
        cudaEventCreateWithFlags(&evFork, cudaEventDisableTiming);
        cudaEventCreateWithFlags(&evJA, cudaEventDisableTiming);
        cudaEventCreateWithFlags(&evJB, cudaEventDisableTiming);
        cudaEventCreateWithFlags(&evJR, cudaEventDisableTiming);
        for (int i = 0; i < 8; i++) {
            cudaEventCreateWithFlags(&evG[i], cudaEventDisableTiming);
            cudaEventCreateWithFlags(&evR[i], cudaEventDisableTiming);
        }
        cudaFuncSetAttribute(recSegK, cudaFuncAttributeMaxDynamicSharedMemorySize, REC_DYN);
        cudaFuncSetAttribute(gateSegK, cudaFuncAttributeMaxDynamicSharedMemorySize, AUX_DYN);
        cudaFuncSetAttribute(outSegK, cudaFuncAttributeMaxDynamicSharedMemorySize, AUX_DYN);
        inited = 1;
    }

    zeroK<<<16, 256>>>();
    precompK<<<1, 128>>>(A, gamma, beta);
    cudaEventRecord(evFork, 0);
    cudaStreamWaitEvent(sA, evFork, 0);
    cudaStreamWaitEvent(sR, evFork, 0);
    cudaStreamWaitEvent(sB, evFork, 0);

    for (int sgi = 0; sgi < 8; sgi++) {
        gateSegK<<<B_*8, 128, AUX_DYN, sA>>>(x, Wsel, bsel, Bm, sgi);
        cudaEventRecord(evG[sgi], sA);
    }
    for (int sgi = 0; sgi < 8; sgi++) {
        cudaStreamWaitEvent(sR, evG[sgi], 0);
        recSegK<<<B_, 256, REC_DYN, sR>>>(A, gamma, beta, sgi);
        cudaEventRecord(evR[sgi], sR);
        cudaStreamWaitEvent(sB, evR[sgi], 0);
        outSegK<<<B_*8, 128, AUX_DYN, sB>>>(x, C, D, out, sgi);
    }
    cudaEventRecord(evJA, sA);
    cudaEventRecord(evJR, sR);
    cudaEventRecord(evJB, sB);
    cudaStreamWaitEvent(0, evJA, 0);
    cudaStreamWaitEvent(0, evJR, 0);
    cudaStreamWaitEvent(0, evJB, 0);

    selFin<<<B_, 128>>>(Wsel, bsel);
    finK<<<1, 256>>>(out);
}

// round 16
// speedup vs baseline: 1.3194x; 1.3194x over previous
#include <cuda_runtime.h>
#include <math.h>

#define B_ 64
#define T_ 2048
#define I_ 64
#define S_ 128
#define O_ 64
#define LN_EPS 1e-5f
#define TP 2052
#define NSEG 16
#define SEGT 128

typedef unsigned long long ull;

__device__ float g_GX[2ull*B_*TP*S_];
__device__ float g_H [B_*T_*S_];
__device__ float g_xsum[B_*I_];
__device__ float g_boSum[B_*O_];
__device__ float g_boSsq[B_*O_];
__device__ float g_S1, g_S2, g_SA;

__device__ __forceinline__ ull pack2(float lo, float hi) {
    ull r; asm("mov.b64 %0,{%1,%2};" : "=l"(r) : "f"(lo), "f"(hi)); return r;
}
__device__ __forceinline__ void unpack2(ull v, float &lo, float &hi) {
    asm("mov.b64 {%0,%1},%2;" : "=f"(lo), "=f"(hi) : "l"(v));
}
__device__ __forceinline__ ull ffma2(ull a, ull b, ull c) {
    ull d; asm("fma.rn.f32x2 %0,%1,%2,%3;" : "=l"(d) : "l"(a), "l"(b), "l"(c)); return d;
}

__global__ void zeroA() {
    int i = blockIdx.x * blockDim.x + threadIdx.x;
    if (i < B_*O_) { g_boSum[i] = 0.f; g_boSsq[i] = 0.f; }
}
__global__ void zeroB() {
    int i = blockIdx.x * blockDim.x + threadIdx.x;
    if (i < B_*I_) g_xsum[i] = 0.f;
    if (i == 0) { g_S1 = 0.f; g_S2 = 0.f; g_SA = 0.f; }
}

// ---------- gateK: fused G+B per thread, 8 tiles/batch (measured 170us) ----------
__global__ __launch_bounds__(128) void gateK(
    const float* __restrict__ x, const float* __restrict__ Wsel,
    const float* __restrict__ bsel, const float* __restrict__ Bm)
{
    __shared__ __align__(16) float xs[2][512];
    __shared__ __align__(16) float xred[128];
    int tid = threadIdx.x;
    int s = tid;
    ull w2G[32], w2B[32];
#pragma unroll
    for (int k = 0; k < 32; k++) {
        w2G[k] = pack2(Wsel[s*I_ + 2*k], Wsel[s*I_ + 2*k+1]);
        w2B[k] = pack2(Bm[s*I_ + 2*k],  Bm[s*I_ + 2*k+1]);
    }
    float bias = bsel[s];

    int b = blockIdx.x >> 3;
    int t0 = (blockIdx.x & 7) << 8;
    const float* xseg = x + ((size_t)b*T_ + t0)*I_;
    float2* outp = ((float2*)g_GX) + (size_t)b*TP*S_ + s;
    float xacc = 0.f;
    int ci = tid & 63, r0 = (tid >> 6) * 4;

    ((float4*)xs[0])[tid] = ((const float4*)xseg)[tid];
    __syncthreads();

    for (int st = 0; st < 32; st++) {
        int cur = st & 1;
        bool more = (st < 31);
        float4 rx = make_float4(0.f, 0.f, 0.f, 0.f);
        if (more) rx = ((const float4*)(xseg + (size_t)(st+1)*512))[tid];
        int tb = t0 + st*8;
#pragma unroll
        for (int r = 0; r < 8; r++) {
            const ulonglong2* xv = (const ulonglong2*)(xs[cur] + r*64);
            ull g0=0, g1=0, b0=0, b1=0;
#pragma unroll
            for (int i = 0; i < 16; i += 2) {
                ulonglong2 p = xv[i], q = xv[i+1];
                g0 = ffma2(w2G[2*i+0], p.x, g0); b0 = ffma2(w2B[2*i+0], p.x, b0);
                g1 = ffma2(w2G[2*i+1], p.y, g1); b1 = ffma2(w2B[2*i+1], p.y, b1);
                g0 = ffma2(w2G[2*i+2], q.x, g0); b0 = ffma2(w2B[2*i+2], q.x, b0);
                g1 = ffma2(w2G[2*i+3], q.y, g1); b1 = ffma2(w2B[2*i+3], q.y, b1);
            }
            float u,v,e,f;
            unpack2(g0,u,v); unpack2(g1,e,f);
            float dg = (u+v)+(e+f);
            unpack2(b0,u,v); unpack2(b1,e,f);
            float db = (u+v)+(e+f);
            float gt = 1.f/(1.f + __expf(-(dg + bias)));
            outp[(size_t)(tb + r)*S_] = make_float2(gt, db);
        }
        xacc += (xs[cur][(r0+0)*64 + ci] + xs[cur][(r0+1)*64 + ci])
              + (xs[cur][(r0+2)*64 + ci] + xs[cur][(r0+3)*64 + ci]);
        __syncthreads();
        if (more) ((float4*)xs[cur ^ 1])[tid] = rx;
        __syncthreads();
    }
    xred[tid] = xacc;
    __syncthreads();
    if (tid < 64) atomicAdd(&g_xsum[b*I_ + tid], xred[tid] + xred[tid+64]);
}

__global__ __launch_bounds__(128) void selFin(
    const float* __restrict__ Wsel, const float* __restrict__ bsel)
{
    __shared__ float part[4];
    int tid = threadIdx.x, b = blockIdx.x;
    float acc = bsel[tid];
    const float invT = 1.0f/(float)T_;
    const float* w  = Wsel + tid*I_;
    const float* xm = g_xsum + b*I_;
#pragma unroll 8
    for (int k = 0; k < I_; k++) acc += xm[k]*invT*w[k];
    float sg = 1.f/(1.f + __expf(-acc));
#pragma unroll
    for (int off = 16; off > 0; off >>= 1) sg += __shfl_xor_sync(0xffffffffu, sg, off);
    if ((tid & 31) == 0) part[tid >> 5] = sg;
    __syncthreads();
    if (tid == 0) atomicAdd(&g_SA, (part[0]+part[1]) + (part[2]+part[3]));
}

// ---------- recK: R14 variant with peeled t=0 (branch-free inner loop) ----------
__global__ __launch_bounds__(256, 1) void recK(
    const float* __restrict__ A, const float* __restrict__ gamma,
    const float* __restrict__ beta)
{
    __shared__ __align__(16) float hbuf[2][136];
    __shared__ __align__(16) float2 red[2][16];
    int tid = threadIdx.x, b = blockIdx.x;
    int w = tid >> 5, lane = tid & 31;
    int s = (w << 4) + (lane >> 1);
    int q = lane & 1;
    int hoff = s + ((s & 64) >> 4);
    const float invS = 1.f/(float)S_;

    float gam_s = gamma[s], bet_s = beta[s];
    float gamI = gam_s * invS;
    float agI = 0.f, abv = 0.f;
    {
        const float* ar = A + s*S_;
#pragma unroll 16
        for (int k = 0; k < S_; k++) { agI += ar[k]*gamma[k]; abv += ar[k]*beta[k]; }
        agI *= invS;
    }
    ull a2[32];
    {
        const float* ar = A + s*S_ + q*64;
        const float* gm = gamma + q*64;
#pragma unroll
        for (int k = 0; k < 32; k++)
            a2[k] = pack2(ar[2*k]*gm[2*k], ar[2*k+1]*gm[2*k+1]);
    }

    const float2* GX = ((const float2*)g_GX) + (size_t)b*TP*S_ + s;
    float* Hp = g_H + (size_t)b*T_*S_ + s;
    float2 gx[4];
#pragma unroll
    for (int j = 0; j < 4; j++) gx[j] = GX[(size_t)j*S_];

    // ---- peeled t = 0: h_{-1} = 0 -> dot = 0, stats = 0, h0 = g0 * xb0 ----
    float hbmine;
    {
        float2 g0v = gx[0];
        gx[0] = GX[(size_t)4*S_];
        hbmine = g0v.x * g0v.y;
        if (!q) hbuf[1][hoff] = hbmine;
        float s1 = hbmine, s2 = hbmine*hbmine;
#pragma unroll
        for (int off = 16; off > 2; off >>= 1) {
            s1 += __shfl_xor_sync(0xffffffffu, s1, off);
            s2 += __shfl_xor_sync(0xffffffffu, s2, off);
        }
        if ((lane & 0x1D) == 0) red[1][2*w + (lane >> 1)] = make_float2(s1, s2);
        __syncthreads();
    }

    int p = 1;
#pragma unroll 4
    for (int t = 1; t < T_; t++) {
        float2 gxv = gx[t & 3];
        gx[t & 3] = GX[(size_t)(t + 4)*S_];

        const float4* rp = (const float4*)red[p];
        float4 r0 = rp[0], r1 = rp[1], r2 = rp[2], r3 = rp[3];
        float4 r4 = rp[4], r5 = rp[5], r6 = rp[6], r7 = rp[7];
        float sum = (((r0.x + r0.z) + (r1.x + r1.z)) + ((r2.x + r2.z) + (r3.x + r3.z)))
                  + (((r4.x + r4.z) + (r5.x + r5.z)) + ((r6.x + r6.z) + (r7.x + r7.z)));
        float ssq = (((r0.y + r0.w) + (r1.y + r1.w)) + ((r2.y + r2.w) + (r3.y + r3.w)))
                  + (((r4.y + r4.w) + (r5.y + r5.w)) + ((r6.y + r6.w) + (r7.y + r7.w)));
        float mu  = sum * invS;
        float ve  = fmaf(ssq, invS, LN_EPS) - mu*mu;
        float rin = rsqrtf(ve);

        const ulonglong2* hv = (const ulonglong2*)(&hbuf[p][q*68]);
        ull ac0 = 0, ac1 = 0, ac2 = 0, ac3 = 0;
#pragma unroll
        for (int i = 0; i < 16; i += 4) {
            ulonglong2 pv = hv[i], rv = hv[i+1], uv = hv[i+2], vv = hv[i+3];
            ac0 = ffma2(a2[2*i+0], pv.x, ac0); ac1 = ffma2(a2[2*i+1], pv.y, ac1);
            ac2 = ffma2(a2[2*i+2], rv.x, ac2); ac3 = ffma2(a2[2*i+3], rv.y, ac3);
            ac0 = ffma2(a2[2*i+4], uv.x, ac0); ac1 = ffma2(a2[2*i+5], uv.y, ac1);
            ac2 = ffma2(a2[2*i+6], vv.x, ac2); ac3 = ffma2(a2[2*i+7], vv.y, ac3);
        }
        float p0,p1,p2,p3,p4,p5,p6,p7;
        unpack2(ac0,p0,p1); unpack2(ac1,p2,p3); unpack2(ac2,p4,p5); unpack2(ac3,p6,p7);
        float dmine = ((p0+p1)+(p2+p3)) + ((p4+p5)+(p6+p7));
        float dfull = dmine + __shfl_xor_sync(0xffffffffu, dmine, 1);

        float abx  = abv + gxv.y;
        float preh = hbmine * gam_s;
        float hpn = fmaf(fmaf(-sum, gamI, preh), rin, bet_s);
        float nextraw = fmaf(fmaf(-sum, agI, dfull), rin, abx);
        float hb = fmaf(gxv.x, nextraw - hpn, hpn);
        if (!q) Hp[(size_t)(t-1)*S_] = hpn;
        if (!q) hbuf[p ^ 1][hoff] = hb;
        hbmine = hb;

        float s1 = hb, s2 = hb*hb;
#pragma unroll
        for (int off = 16; off > 2; off >>= 1) {
            s1 += __shfl_xor_sync(0xffffffffu, s1, off);
            s2 += __shfl_xor_sync(0xffffffffu, s2, off);
        }
        if ((lane & 0x1D) == 0) red[p ^ 1][2*w + (lane >> 1)] = make_float2(s1, s2);
        __syncthreads();
        p ^= 1;
    }

    {
        const float4* rp = (const float4*)red[p];
        float4 r0 = rp[0], r1 = rp[1], r2 = rp[2], r3 = rp[3];
        float4 r4 = rp[4], r5 = rp[5], r6 = rp[6], r7 = rp[7];
        float sum = (((r0.x + r0.z) + (r1.x + r1.z)) + ((r2.x + r2.z) + (r3.x + r3.z)))
                  + (((r4.x + r4.z) + (r5.x + r5.z)) + ((r6.x + r6.z) + (r7.x + r7.z)));
        float ssq = (((r0.y + r0.w) + (r1.y + r1.w)) + ((r2.y + r2.w) + (r3.y + r3.w)))
                  + (((r4.y + r4.w) + (r5.y + r5.w)) + ((r6.y + r6.w) + (r7.y + r7.w)));
        float mu  = sum * invS;
        float ve  = fmaf(ssq, invS, LN_EPS) - mu*mu;
        float rin = rsqrtf(ve);
        float hpn = fmaf(fmaf(-sum, gamI, hbmine*gam_s), rin, bet_s);
        if (!q) Hp[(size_t)(T_-1)*S_] = hpn;
    }
}

// ---------- outK: hf-split + register double-buffer prefetch (measured 193us) ----------
__global__ __launch_bounds__(128) void outK(
    const float* __restrict__ x, const float* __restrict__ C,
    const float* __restrict__ D, float* __restrict__ out)
{
    __shared__ __align__(16) float Hs[512];
    __shared__ __align__(16) float xsO[256];
    __shared__ __align__(16) float Ysf[4][64];
    __shared__ __align__(16) float Ys2f[4][64];
    __shared__ __align__(16) float ypS[64];

    int tid = threadIdx.x;
    int b = blockIdx.x >> 4, seg = blockIdx.x & 15;
    int o = tid & 63, hf = tid >> 6;
    int w = tid >> 5, lane = tid & 31;

    ull c2[32], d2[16];
#pragma unroll
    for (int k = 0; k < 32; k++)
        c2[k] = pack2(C[o*S_ + hf*64 + 2*k], C[o*S_ + hf*64 + 2*k+1]);
#pragma unroll
    for (int k = 0; k < 16; k++)
        d2[k] = pack2(D[o*I_ + hf*32 + 2*k], D[o*I_ + hf*32 + 2*k+1]);
    float* dsth = hf ? &Ys2f[0][0] : &Ysf[0][0];
    float boS=0.f, boQ=0.f, nrmAcc=0.f, difAcc=0.f, ylastR=0.f;
    int t0 = seg << 7;

    const float* Hb = g_H + (size_t)b*T_*S_;
    const float* xb = x + (size_t)b*T_*I_;

    if (seg > 0) {
        Hs[tid] = Hb[(size_t)(t0-1)*S_ + tid];
        if (tid < 64) xsO[tid] = xb[(size_t)(t0-1)*I_ + tid];
        __syncthreads();
        {
            const ull* hv = (const ull*)(Hs + hf*64);
            const ull* xv = (const ull*)(xsO + hf*32);
            ull a0=0, a1=0;
#pragma unroll
            for (int k = 0; k < 32; k += 2) {
                a0 = ffma2(c2[k], hv[k], a0); a1 = ffma2(c2[k+1], hv[k+1], a1);
            }
#pragma unroll
            for (int k = 0; k < 16; k += 2) {
                a0 = ffma2(d2[k], xv[k], a0); a1 = ffma2(d2[k+1], xv[k+1], a1);
            }
            float u,v,e,f2; unpack2(a0,u,v); unpack2(a1,e,f2);
            dsth[o] = (u+v)+(e+f2);
        }
        __syncthreads();
        if (tid < 64) ylastR = Ysf[0][tid] + Ys2f[0][tid];
    }

    float pH[4], px0, px1;
#pragma unroll
    for (int j = 0; j < 4; j++) pH[j] = Hb[(size_t)(t0 + j)*S_ + tid];
    px0 = xb[(size_t)(t0 +     (tid >> 6))*I_ + o];
    px1 = xb[(size_t)(t0 + 2 + (tid >> 6))*I_ + o];

    for (int g = 0; g < SEGT/4; g++) {
        int tbase = t0 + (g << 2);
        __syncthreads();
        if (tid < 64) ypS[tid] = ylastR;
#pragma unroll
        for (int j = 0; j < 4; j++) Hs[j*128 + tid] = pH[j];
        xsO[tid]       = px0;
        xsO[tid + 128] = px1;
        __syncthreads();

        if (g + 1 < SEGT/4) {
            int tn = tbase + 4;
#pragma unroll
            for (int j = 0; j < 4; j++) pH[j] = Hb[(size_t)(tn + j)*S_ + tid];
            px0 = xb[(size_t)(tn +     (tid >> 6))*I_ + o];
            px1 = xb[(size_t)(tn + 2 + (tid >> 6))*I_ + o];
        }
#pragma unroll
        for (int r = 0; r < 4; r++) {
            const ull* hv = (const ull*)(Hs + r*128 + hf*64);
            const ull* xv = (const ull*)(xsO + r*64 + hf*32);
            ull a0=0, a1=0, a2b=0, a3=0;
#pragma unroll
            for (int k = 0; k < 32; k += 4) {
                a0  = ffma2(c2[k],   hv[k],   a0);
                a1  = ffma2(c2[k+1], hv[k+1], a1);
                a2b = ffma2(c2[k+2], hv[k+2], a2b);
                a3  = ffma2(c2[k+3], hv[k+3], a3);
            }
#pragma unroll
            for (int k = 0; k < 16; k += 4) {
                a0  = ffma2(d2[k],   xv[k],   a0);
                a1  = ffma2(d2[k+1], xv[k+1], a1);
                a2b = ffma2(d2[k+2], xv[k+2], a2b);
                a3  = ffma2(d2[k+3], xv[k+3], a3);
            }
            float u,v,e,f2,m,n,pp,qq;
            unpack2(a0,u,v); unpack2(a1,e,f2); unpack2(a2b,m,n); unpack2(a3,pp,qq);
            dsth[r*64 + o] = ((u+v)+(e+f2)) + ((m+n)+(pp+qq));
        }
        __syncthreads();
#pragma unroll
        for (int rr = 0; rr < 2; rr++) {
            int r = hf + rr*2;
            float y = Ysf[r][o] + Ys2f[r][o];
            Ysf[r][o] = y;
            boS += y; boQ += y*y;
            if (tbase + r == T_-1) out[b*O_ + o] = y;
        }
        __syncthreads();
        {
            float y0 = Ysf[w][lane], y1 = Ysf[w][lane+32];
            float p0, p1;
            if (w == 0) { p0 = ypS[lane]; p1 = ypS[lane+32]; }
            else        { p0 = Ysf[w-1][lane]; p1 = Ysf[w-1][lane+32]; }
            float sn = y0*y0 + y1*y1;
            float d0 = y0 - p0, d1 = y1 - p1;
            float dn = d0*d0 + d1*d1;
#pragma unroll
            for (int off = 16; off > 0; off >>= 1) {
                sn += __shfl_xor_sync(0xffffffffu, sn, off);
                dn += __shfl_xor_sync(0xffffffffu, dn, off);
            }
            if (lane == 0) {
                nrmAcc += sqrtf(sn);
                if (tbase + w > 0) difAcc += sqrtf(dn);
            }
            if (tid < 64) ylastR = Ysf[3][tid];
        }
    }

    if (lane == 0) { atomicAdd(&g_S2, nrmAcc); atomicAdd(&g_S1, difAcc); }
    __syncthreads();
    Hs[tid] = boS;
    __syncthreads();
    if (tid < 64) atomicAdd(&g_boSum[b*O_ + tid], Hs[tid] + Hs[tid+64]);
    __syncthreads();
    Hs[tid] = boQ;
    __syncthreads();
    if (tid < 64) atomicAdd(&g_boSsq[b*O_ + tid], Hs[tid] + Hs[tid+64]);
}

__global__ void finK(float* __restrict__ out)
{
    __shared__ float part[8];
    int tid = threadIdx.x;
    float acc = 0.f;
    for (int idx = tid; idx < B_*O_; idx += 256) {
        float sum = g_boSum[idx], ssq = g_boSsq[idx];
        float var = (ssq - sum*sum*(1.f/T_)) * (1.f/(T_ - 1));
        acc += sqrtf(fmaxf(var, 0.f));
    }
#pragma unroll
    for (int off = 16; off > 0; off >>= 1) acc += __shfl_xor_sync(0xffffffffu, acc, off);
    if ((tid & 31) == 0) part[tid >> 5] = acc;
    __syncthreads();
    if (tid == 0) {
        float tot = 0.f;
#pragma unroll
        for (int k = 0; k < 8; k++) tot += part[k];
        out[4096] = 1.f / (1.f + g_S1 / (float)(B_*(T_-1)));
        out[4097] = g_S2 / (float)(B_*T_);
        out[4098] = g_SA / (float)(B_*S_);
        out[4099] = tot  / (float)(B_*O_);
    }
}

extern "C" void kernel_launch(void* const* d_in, const int* in_sizes, int n_in,
                              void* d_out, int out_size)
{
    const float* x     = (const float*)d_in[0];
    const float* A     = (const float*)d_in[1];
    const float* Bm    = (const float*)d_in[2];
    const float* C     = (const float*)d_in[3];
    const float* D     = (const float*)d_in[4];
    const float* Wsel  = (const float*)d_in[5];
    const float* bsel  = (const float*)d_in[6];
    const float* gamma = (const float*)d_in[7];
    const float* beta  = (const float*)d_in[8];
    float* out = (float*)d_out;

    zeroA<<<16, 256>>>();
    zeroB<<<16, 256>>>();
    gateK<<<B_*8, 128>>>(x, Wsel, bsel, Bm);
    recK<<<B_, 256>>>(A, gamma, beta);      // profiled slot
    outK<<<B_*NSEG, 128>>>(x, C, D, out);
    selFin<<<B_, 128>>>(Wsel, bsel);
    finK<<<1, 256>>>(out);
}